// round 2
// baseline (speedup 1.0000x reference)
#include <cuda_runtime.h>
#include <cuda_bf16.h>
#include <cstdint>

#define L_SEQ 2048
#define DE    2048
#define DMLP  8192
#define NH    16
#define DA    128

#define BM 128
#define BN 128
#define BK 64
#define GEMM_SMEM (2*BM*128 + 2*BN*128)   // 65536 bytes

// ---------------- static device scratch (allocation-free) ----------------
static __device__ __align__(256) __nv_bfloat16 g_xn1 [(size_t)L_SEQ*DE];
static __device__ __align__(256) __nv_bfloat16 g_xn2 [(size_t)L_SEQ*DE];
static __device__ __align__(256) float         g_xn2f[(size_t)L_SEQ*DE];
static __device__ __align__(256) float         g_x2  [(size_t)L_SEQ*DE];
static __device__ __align__(256) __nv_bfloat16 g_Wqt [(size_t)NH*DA*DE];
static __device__ __align__(256) __nv_bfloat16 g_Wkt [(size_t)NH*DA*DE];
static __device__ __align__(256) __nv_bfloat16 g_Wv15t[(size_t)DA*DE];
static __device__ __align__(256) float         g_Wv0 [(size_t)15*DE];
static __device__ __align__(256) float         g_v0  [(size_t)15*L_SEQ];
static __device__ __align__(256) __nv_bfloat16 g_q   [(size_t)NH*L_SEQ*DA];
static __device__ __align__(256) __nv_bfloat16 g_k   [(size_t)NH*L_SEQ*DA];
static __device__ __align__(256) __nv_bfloat16 g_v15 [(size_t)L_SEQ*DA];
static __device__ __align__(256) __nv_bfloat16 g_v15t[(size_t)DA*L_SEQ];
static __device__ __align__(256) __nv_bfloat16 g_E   [(size_t)NH*L_SEQ*L_SEQ];
static __device__ __align__(256) float         g_den [(size_t)NH*L_SEQ];
static __device__ __align__(256) __nv_bfloat16 g_yc  [(size_t)L_SEQ*256];
static __device__ __align__(256) __nv_bfloat16 g_Wot [(size_t)DE*256];
static __device__ __align__(256) __nv_bfloat16 g_W1t [(size_t)DMLP*DE];
static __device__ __align__(256) __nv_bfloat16 g_W2t [(size_t)DE*DMLP];
static __device__ __align__(256) __nv_bfloat16 g_h1  [(size_t)L_SEQ*DMLP];

// ---------------- helpers ----------------
__device__ __forceinline__ void cpasync16(uint32_t dst, const void* src) {
    asm volatile("cp.async.cg.shared.global [%0], [%1], 16;\n" :: "r"(dst), "l"(src));
}
__device__ __forceinline__ void cpcommit() { asm volatile("cp.async.commit_group;\n"); }
template<int N> __device__ __forceinline__ void cpwait() {
    asm volatile("cp.async.wait_group %0;\n" :: "n"(N));
}
__device__ __forceinline__ void ldsm4(uint32_t* r, uint32_t addr) {
    asm volatile("ldmatrix.sync.aligned.m8n8.x4.shared.b16 {%0,%1,%2,%3}, [%4];\n"
                 : "=r"(r[0]), "=r"(r[1]), "=r"(r[2]), "=r"(r[3]) : "r"(addr));
}
__device__ __forceinline__ void mma16816(float* c, const uint32_t* a, uint32_t b0, uint32_t b1) {
    asm volatile("mma.sync.aligned.m16n8k16.row.col.f32.bf16.bf16.f32 "
                 "{%0,%1,%2,%3}, {%4,%5,%6,%7}, {%8,%9}, {%0,%1,%2,%3};\n"
                 : "+f"(c[0]), "+f"(c[1]), "+f"(c[2]), "+f"(c[3])
                 : "r"(a[0]), "r"(a[1]), "r"(a[2]), "r"(a[3]), "r"(b0), "r"(b1));
}
__device__ __forceinline__ float fast_exp(float t) {
    if (fabsf(t) < 0.25f) return 1.f + t * (1.f + t * (0.5f + t * 0.16666667f));
    return expf(t);
}
__device__ __forceinline__ float gelu_tanh(float u) {
    float u2 = u * u;
    float w  = 0.7978845608028654f * u * (1.f + 0.044715f * u2);
    float t;
    if (fabsf(w) < 0.5f) {
        float w2 = w * w;
        t = w * (1.f - w2 * (0.33333333f - w2 * (0.13333333f - w2 * 0.05396825f)));
    } else {
        t = tanhf(w);
    }
    return 0.5f * u * (1.f + t);
}

// ---------------- generic bf16 GEMM: C = A(MxK) * B(NxK)^T, f32 accum ----------------
// Epilogues:
// 0: bf16 C = acc + bias[n]
// 1: bf16 C = exp(acc*scale)
// 2: bf16 yc[m*ldc + 15+n] = acc / den[m]
// 3: f32  C = 2*aux1 + acc + bias[n]
// 4: bf16 C = gelu(acc + bias[n])
// 5: f32  C = acc + bias[n] + aux1 + aux2
struct GP {
    const __nv_bfloat16* A; int lda; long sA;
    const __nv_bfloat16* B; int ldb; long sB;
    int K;
    const float* bias; int sBias;
    void* C; int ldc; long sC;
    const float* aux1;
    const float* aux2;
    const float* den;
    float scale;
};

template<int EPI>
__global__ void __launch_bounds__(256) gemm_bf16(GP p) {
    extern __shared__ __align__(128) char smem[];
    const int tid = threadIdx.x;
    const int bm = blockIdx.x * BM;
    const int bn = blockIdx.y * BN;
    const int z  = blockIdx.z;

    const __nv_bfloat16* Ag = p.A + (long)z * p.sA;
    const __nv_bfloat16* Bg = p.B + (long)z * p.sB;

    uint32_t sbase = (uint32_t)__cvta_generic_to_shared(smem);
    const uint32_t sAb = sbase;
    const uint32_t sBb = sbase + 2 * BM * 128;

    const int lr = tid >> 3;      // 0..31
    const int lc = tid & 7;       // 16B chunk 0..7
    const __nv_bfloat16* Agp = Ag + (long)(bm + lr) * p.lda + lc * 8;
    const __nv_bfloat16* Bgp = Bg + (long)(bn + lr) * p.ldb + lc * 8;

    float c[2][8][4];
    #pragma unroll
    for (int i = 0; i < 2; i++)
        #pragma unroll
        for (int j = 0; j < 8; j++)
            #pragma unroll
            for (int r = 0; r < 4; r++) c[i][j][r] = 0.f;

    const int KT = p.K / BK;

    #pragma unroll
    for (int i = 0; i < 4; i++) {
        int r = lr + 32 * i;
        cpasync16(sAb + r * 128 + ((lc * 16) ^ ((r & 7) * 16)), Agp + (long)(32 * i) * p.lda);
    }
    #pragma unroll
    for (int i = 0; i < 4; i++) {
        int r = lr + 32 * i;
        cpasync16(sBb + r * 128 + ((lc * 16) ^ ((r & 7) * 16)), Bgp + (long)(32 * i) * p.ldb);
    }
    cpcommit();

    const int lane = tid & 31, warp = tid >> 5;
    const int wm = warp & 3, wn = warp >> 2;

    for (int kt = 0; kt < KT; kt++) {
        if (kt + 1 < KT) {
            uint32_t aS = sAb + ((kt + 1) & 1) * BM * 128;
            uint32_t bS = sBb + ((kt + 1) & 1) * BM * 128;
            const __nv_bfloat16* Ak = Agp + (kt + 1) * BK;
            const __nv_bfloat16* Bk = Bgp + (kt + 1) * BK;
            #pragma unroll
            for (int i = 0; i < 4; i++) {
                int r = lr + 32 * i;
                cpasync16(aS + r * 128 + ((lc * 16) ^ ((r & 7) * 16)), Ak + (long)(32 * i) * p.lda);
            }
            #pragma unroll
            for (int i = 0; i < 4; i++) {
                int r = lr + 32 * i;
                cpasync16(bS + r * 128 + ((lc * 16) ^ ((r & 7) * 16)), Bk + (long)(32 * i) * p.ldb);
            }
            cpcommit();
            cpwait<1>();
        } else {
            cpwait<0>();
        }
        __syncthreads();

        uint32_t aS = sAb + (kt & 1) * BM * 128;
        uint32_t bS = sBb + (kt & 1) * BM * 128;
        #pragma unroll
        for (int ks = 0; ks < 4; ks++) {
            uint32_t a[2][4];
            #pragma unroll
            for (int i = 0; i < 2; i++) {
                int r  = wm * 32 + i * 16 + (lane & 15);
                int cb = ks * 32 + ((lane >> 4) << 4);
                ldsm4(a[i], aS + r * 128 + (cb ^ ((r & 7) << 4)));
            }
            #pragma unroll
            for (int j4 = 0; j4 < 4; j4++) {
                uint32_t b[4];
                int n  = wn * 64 + j4 * 16 + ((lane >> 4) << 3) + (lane & 7);
                int cb = ks * 32 + (((lane >> 3) & 1) << 4);
                ldsm4(b, bS + n * 128 + (cb ^ ((n & 7) << 4)));
                #pragma unroll
                for (int i = 0; i < 2; i++) {
                    mma16816(c[i][2 * j4],     a[i], b[0], b[1]);
                    mma16816(c[i][2 * j4 + 1], a[i], b[2], b[3]);
                }
            }
        }
        __syncthreads();
    }

    const int row0 = lane >> 2, col0 = (lane & 3) * 2;

    #pragma unroll
    for (int i = 0; i < 2; i++)
        #pragma unroll
        for (int j = 0; j < 8; j++)
            #pragma unroll
            for (int h2 = 0; h2 < 2; h2++) {
                long gm = bm + wm * 32 + i * 16 + h2 * 8 + row0;
                long gn = bn + wn * 64 + j * 8 + col0;
                float a0 = c[i][j][h2 * 2 + 0];
                float a1 = c[i][j][h2 * 2 + 1];

                if (EPI == 0 || EPI == 4) {
                    __nv_bfloat16* C = (__nv_bfloat16*)p.C + (long)z * p.sC;
                    const float* bias = p.bias + (long)z * p.sBias;
                    float x0 = a0 + bias[gn], x1 = a1 + bias[gn + 1];
                    if (EPI == 4) { x0 = gelu_tanh(x0); x1 = gelu_tanh(x1); }
                    __nv_bfloat162 pk;
                    pk.x = __float2bfloat16(x0); pk.y = __float2bfloat16(x1);
                    *reinterpret_cast<__nv_bfloat162*>(&C[gm * p.ldc + gn]) = pk;
                } else if (EPI == 1) {
                    __nv_bfloat16* C = (__nv_bfloat16*)p.C + (long)z * p.sC;
                    __nv_bfloat162 pk;
                    pk.x = __float2bfloat16(fast_exp(a0 * p.scale));
                    pk.y = __float2bfloat16(fast_exp(a1 * p.scale));
                    *reinterpret_cast<__nv_bfloat162*>(&C[gm * p.ldc + gn]) = pk;
                } else if (EPI == 2) {
                    __nv_bfloat16* C = (__nv_bfloat16*)p.C;
                    float rd = 1.f / p.den[gm];
                    C[gm * p.ldc + 15 + gn]     = __float2bfloat16(a0 * rd);
                    C[gm * p.ldc + 15 + gn + 1] = __float2bfloat16(a1 * rd);
                } else if (EPI == 3) {
                    float* C = (float*)p.C;
                    long i0 = gm * p.ldc + gn;
                    C[i0]     = 2.f * p.aux1[i0]     + a0 + p.bias[gn];
                    C[i0 + 1] = 2.f * p.aux1[i0 + 1] + a1 + p.bias[gn + 1];
                } else if (EPI == 5) {
                    float* C = (float*)p.C;
                    long i0 = gm * p.ldc + gn;
                    C[i0]     = a0 + p.bias[gn]     + p.aux1[i0]     + p.aux2[i0];
                    C[i0 + 1] = a1 + p.bias[gn + 1] + p.aux1[i0 + 1] + p.aux2[i0 + 1];
                }
            }
}

// ---------------- layernorm (population std, matches jnp.std) ----------------
__global__ void ln_kernel(const float* __restrict__ x, const float* __restrict__ g,
                          const float* __restrict__ b, __nv_bfloat16* ob, float* of) {
    int l = blockIdx.x, tid = threadIdx.x;
    const float* row = x + (long)l * DE;
    float v[8], s = 0.f, s2 = 0.f;
    #pragma unroll
    for (int j = 0; j < 8; j++) {
        v[j] = row[tid + 256 * j];
        s += v[j]; s2 += v[j] * v[j];
    }
    __shared__ float sm[18];
    #pragma unroll
    for (int o = 16; o; o >>= 1) {
        s  += __shfl_xor_sync(0xffffffffu, s,  o);
        s2 += __shfl_xor_sync(0xffffffffu, s2, o);
    }
    if ((tid & 31) == 0) { sm[tid >> 5] = s; sm[(tid >> 5) + 8] = s2; }
    __syncthreads();
    if (tid == 0) {
        float a = 0.f, q = 0.f;
        #pragma unroll
        for (int i = 0; i < 8; i++) { a += sm[i]; q += sm[i + 8]; }
        float mean = a / DE;
        float var  = q / DE - mean * mean;
        float sd   = sqrtf(fmaxf(var, 0.f));
        if (sd == 0.f) sd = 1.f;
        sm[16] = mean; sm[17] = 1.f / sd;
    }
    __syncthreads();
    float mean = sm[16], rs = sm[17];
    #pragma unroll
    for (int j = 0; j < 8; j++) {
        int col = tid + 256 * j;
        float y = g[col] * ((v[j] - mean) * rs) + b[col];
        ob[(long)l * DE + col] = __float2bfloat16(y);
        if (of) of[(long)l * DE + col] = y;
    }
}

// ---------------- v0 matvecs: v0[h][l] = xn1[l]·Wv[h][:,0] + bv[h][0], h<15 ----------------
__global__ void v0_kernel(const __nv_bfloat16* __restrict__ xn1, const float* __restrict__ Wv0,
                          const float* __restrict__ bv, float* __restrict__ v0) {
    int l = blockIdx.x, tid = threadIdx.x;
    __shared__ float xr[DE];
    __shared__ float sm[8];
    for (int k = tid; k < DE; k += 256) xr[k] = __bfloat162float(xn1[(long)l * DE + k]);
    __syncthreads();
    for (int h = 0; h < 15; h++) {
        const float* w = Wv0 + (long)h * DE;
        float p = 0.f;
        for (int k = tid; k < DE; k += 256) p += xr[k] * w[k];
        #pragma unroll
        for (int o = 16; o; o >>= 1) p += __shfl_xor_sync(0xffffffffu, p, o);
        if ((tid & 31) == 0) sm[tid >> 5] = p;
        __syncthreads();
        if (tid == 0) {
            float a = 0.f;
            #pragma unroll
            for (int i = 0; i < 8; i++) a += sm[i];
            v0[(long)h * L_SEQ + l] = a + bv[h * DA];
        }
        __syncthreads();
    }
}

// ---------------- attention reduce: den + head<15 numerators ----------------
__global__ void attn_reduce(const __nv_bfloat16* __restrict__ E, const float* __restrict__ v0,
                            float* __restrict__ den, __nv_bfloat16* __restrict__ yc) {
    int l = blockIdx.x, h = blockIdx.y, tid = threadIdx.x;
    const __nv_bfloat162* row2 =
        reinterpret_cast<const __nv_bfloat162*>(E + ((long)h * L_SEQ + l) * L_SEQ);
    bool last = (h == NH - 1);
    const float* vv = v0 + (long)h * L_SEQ;
    float s = 0.f, d = 0.f;
    for (int m = tid; m < L_SEQ / 2; m += 256) {
        float2 e = __bfloat1622float2(row2[m]);
        s += e.x + e.y;
        if (!last) d += e.x * vv[2 * m] + e.y * vv[2 * m + 1];
    }
    __shared__ float sa[8], sb[8];
    #pragma unroll
    for (int o = 16; o; o >>= 1) {
        s += __shfl_xor_sync(0xffffffffu, s, o);
        d += __shfl_xor_sync(0xffffffffu, d, o);
    }
    if ((tid & 31) == 0) { sa[tid >> 5] = s; sb[tid >> 5] = d; }
    __syncthreads();
    if (tid == 0) {
        float as = 0.f, ad = 0.f;
        #pragma unroll
        for (int i = 0; i < 8; i++) { as += sa[i]; ad += sb[i]; }
        den[(long)h * L_SEQ + l] = as;
        if (!last) yc[(long)l * 256 + h] = __float2bfloat16(ad / as);
    }
}

// ---------------- weight prep ----------------
__global__ void transpose_cvt(const float* __restrict__ src, __nv_bfloat16* __restrict__ dst,
                              int R, int C, long sS, long sD) {
    __shared__ float t[32][33];
    src += (long)blockIdx.z * sS;
    dst += (long)blockIdx.z * sD;
    int c0 = blockIdx.x * 32, r0 = blockIdx.y * 32;
    int tx = threadIdx.x, ty = threadIdx.y;
    for (int i = ty; i < 32; i += 8) t[i][tx] = src[(long)(r0 + i) * C + c0 + tx];
    __syncthreads();
    for (int i = ty; i < 32; i += 8)
        dst[(long)(c0 + i) * R + r0 + tx] = __float2bfloat16(t[tx][i]);
}

__global__ void wo_prep(const float* __restrict__ Wo, __nv_bfloat16* __restrict__ Wot) {
    long idx = (long)blockIdx.x * 256 + threadIdx.x;   // over 256*2048
    int k = (int)(idx >> 11), n = (int)(idx & 2047);
    float v = (k < 143) ? Wo[(long)k * DE + n] : 0.f;
    Wot[(long)n * 256 + k] = __float2bfloat16(v);
}

__global__ void wv0_prep(const float* __restrict__ Wv, float* __restrict__ Wv0) {
    long idx = (long)blockIdx.x * 256 + threadIdx.x;   // over 15*2048
    if (idx < 15 * DE) {
        long h = idx / DE, k = idx % DE;
        Wv0[idx] = Wv[(h * DE + k) * DA];
    }
}

__global__ void zero_yc(__nv_bfloat16* yc) {
    long idx = (long)blockIdx.x * 256 + threadIdx.x;   // over 2048*256
    yc[idx] = __float2bfloat16(0.f);
}

__global__ void t_v15(const __nv_bfloat16* __restrict__ src, __nv_bfloat16* __restrict__ dst) {
    long idx = (long)blockIdx.x * 256 + threadIdx.x;   // over 2048*128
    int l = (int)(idx >> 7), v = (int)(idx & 127);
    dst[(long)v * L_SEQ + l] = src[idx];
}

// ---------------- host launcher ----------------
static void launch_gemm(int epi, const GP& p, int M, int N, int Z) {
    dim3 grid(M / BM, N / BN, Z), block(256);
    switch (epi) {
        case 0: cudaFuncSetAttribute(gemm_bf16<0>, cudaFuncAttributeMaxDynamicSharedMemorySize, GEMM_SMEM);
                gemm_bf16<0><<<grid, block, GEMM_SMEM>>>(p); break;
        case 1: cudaFuncSetAttribute(gemm_bf16<1>, cudaFuncAttributeMaxDynamicSharedMemorySize, GEMM_SMEM);
                gemm_bf16<1><<<grid, block, GEMM_SMEM>>>(p); break;
        case 2: cudaFuncSetAttribute(gemm_bf16<2>, cudaFuncAttributeMaxDynamicSharedMemorySize, GEMM_SMEM);
                gemm_bf16<2><<<grid, block, GEMM_SMEM>>>(p); break;
        case 3: cudaFuncSetAttribute(gemm_bf16<3>, cudaFuncAttributeMaxDynamicSharedMemorySize, GEMM_SMEM);
                gemm_bf16<3><<<grid, block, GEMM_SMEM>>>(p); break;
        case 4: cudaFuncSetAttribute(gemm_bf16<4>, cudaFuncAttributeMaxDynamicSharedMemorySize, GEMM_SMEM);
                gemm_bf16<4><<<grid, block, GEMM_SMEM>>>(p); break;
        case 5: cudaFuncSetAttribute(gemm_bf16<5>, cudaFuncAttributeMaxDynamicSharedMemorySize, GEMM_SMEM);
                gemm_bf16<5><<<grid, block, GEMM_SMEM>>>(p); break;
    }
}

extern "C" void kernel_launch(void* const* d_in, const int* in_sizes, int n_in,
                              void* d_out, int out_size) {
    const float* x      = (const float*)d_in[0];
    const float* Wq     = (const float*)d_in[1];
    const float* bq     = (const float*)d_in[2];
    const float* Wk     = (const float*)d_in[3];
    const float* bk     = (const float*)d_in[4];
    const float* Wv     = (const float*)d_in[5];
    const float* bv     = (const float*)d_in[6];
    const float* Wo     = (const float*)d_in[7];
    const float* bo     = (const float*)d_in[8];
    const float* gamma1 = (const float*)d_in[9];
    const float* beta1  = (const float*)d_in[10];
    const float* gamma2 = (const float*)d_in[11];
    const float* beta2  = (const float*)d_in[12];
    const float* W1     = (const float*)d_in[13];
    const float* b1     = (const float*)d_in[14];
    const float* W2     = (const float*)d_in[15];
    const float* b2     = (const float*)d_in[16];
    float* out = (float*)d_out;

    void *p_xn1, *p_xn2, *p_xn2f, *p_x2, *p_Wqt, *p_Wkt, *p_Wv15t, *p_Wv0, *p_v0;
    void *p_q, *p_k, *p_v15, *p_v15t, *p_E, *p_den, *p_yc, *p_Wot, *p_W1t, *p_W2t, *p_h1;
    cudaGetSymbolAddress(&p_xn1, g_xn1);   cudaGetSymbolAddress(&p_xn2, g_xn2);
    cudaGetSymbolAddress(&p_xn2f, g_xn2f); cudaGetSymbolAddress(&p_x2, g_x2);
    cudaGetSymbolAddress(&p_Wqt, g_Wqt);   cudaGetSymbolAddress(&p_Wkt, g_Wkt);
    cudaGetSymbolAddress(&p_Wv15t, g_Wv15t); cudaGetSymbolAddress(&p_Wv0, g_Wv0);
    cudaGetSymbolAddress(&p_v0, g_v0);     cudaGetSymbolAddress(&p_q, g_q);
    cudaGetSymbolAddress(&p_k, g_k);       cudaGetSymbolAddress(&p_v15, g_v15);
    cudaGetSymbolAddress(&p_v15t, g_v15t); cudaGetSymbolAddress(&p_E, g_E);
    cudaGetSymbolAddress(&p_den, g_den);   cudaGetSymbolAddress(&p_yc, g_yc);
    cudaGetSymbolAddress(&p_Wot, g_Wot);   cudaGetSymbolAddress(&p_W1t, g_W1t);
    cudaGetSymbolAddress(&p_W2t, g_W2t);   cudaGetSymbolAddress(&p_h1, g_h1);

    __nv_bfloat16* xn1  = (__nv_bfloat16*)p_xn1;
    __nv_bfloat16* xn2  = (__nv_bfloat16*)p_xn2;
    float* xn2f = (float*)p_xn2f;
    float* x2   = (float*)p_x2;
    __nv_bfloat16* Wqt  = (__nv_bfloat16*)p_Wqt;
    __nv_bfloat16* Wkt  = (__nv_bfloat16*)p_Wkt;
    __nv_bfloat16* Wv15t= (__nv_bfloat16*)p_Wv15t;
    float* Wv0  = (float*)p_Wv0;
    float* v0   = (float*)p_v0;
    __nv_bfloat16* q    = (__nv_bfloat16*)p_q;
    __nv_bfloat16* k    = (__nv_bfloat16*)p_k;
    __nv_bfloat16* v15  = (__nv_bfloat16*)p_v15;
    __nv_bfloat16* v15t = (__nv_bfloat16*)p_v15t;
    __nv_bfloat16* E    = (__nv_bfloat16*)p_E;
    float* den  = (float*)p_den;
    __nv_bfloat16* yc   = (__nv_bfloat16*)p_yc;
    __nv_bfloat16* Wot  = (__nv_bfloat16*)p_Wot;
    __nv_bfloat16* W1t  = (__nv_bfloat16*)p_W1t;
    __nv_bfloat16* W2t  = (__nv_bfloat16*)p_W2t;
    __nv_bfloat16* h1   = (__nv_bfloat16*)p_h1;

    dim3 tb(32, 8);

    // ---- weight prep ----
    transpose_cvt<<<dim3(DA/32, DE/32, NH), tb>>>(Wq, Wqt, DE, DA, (long)DE*DA, (long)DA*DE);
    transpose_cvt<<<dim3(DA/32, DE/32, NH), tb>>>(Wk, Wkt, DE, DA, (long)DE*DA, (long)DA*DE);
    transpose_cvt<<<dim3(DA/32, DE/32, 1),  tb>>>(Wv + (long)15*DE*DA, Wv15t, DE, DA, 0, 0);
    transpose_cvt<<<dim3(DMLP/32, DE/32, 1), tb>>>(W1, W1t, DE, DMLP, 0, 0);
    transpose_cvt<<<dim3(DE/32, DMLP/32, 1), tb>>>(W2, W2t, DMLP, DE, 0, 0);
    wo_prep<<<(256 * DE) / 256, 256>>>(Wo, Wot);
    wv0_prep<<<(15 * DE + 255) / 256, 256>>>(Wv, Wv0);
    zero_yc<<<(L_SEQ * 256) / 256, 256>>>(yc);

    // ---- LN1 ----
    ln_kernel<<<L_SEQ, 256>>>(x, gamma1, beta1, xn1, nullptr);

    GP p{};
    const float inv_sqrt_d = 0.08838834764831845f;

    // ---- Q = xn1 @ Wq + bq (batched heads) ----
    p = GP{xn1, DE, 0, Wqt, DE, (long)DA*DE, DE, bq, DA, q, DA, (long)L_SEQ*DA,
           nullptr, nullptr, nullptr, 0.f};
    launch_gemm(0, p, L_SEQ, DA, NH);
    // ---- K ----
    p = GP{xn1, DE, 0, Wkt, DE, (long)DA*DE, DE, bk, DA, k, DA, (long)L_SEQ*DA,
           nullptr, nullptr, nullptr, 0.f};
    launch_gemm(0, p, L_SEQ, DA, NH);
    // ---- V head 15 ----
    p = GP{xn1, DE, 0, Wv15t, DE, 0, DE, bv + 15*DA, 0, v15, DA, 0,
           nullptr, nullptr, nullptr, 0.f};
    launch_gemm(0, p, L_SEQ, DA, 1);
    // ---- v0 matvecs (heads 0..14) ----
    v0_kernel<<<L_SEQ, 256>>>(xn1, Wv0, bv, v0);

    // ---- E = exp(Q K^T / sqrt(d)) (batched heads) ----
    p = GP{q, DA, (long)L_SEQ*DA, k, DA, (long)L_SEQ*DA, DA, nullptr, 0,
           E, L_SEQ, (long)L_SEQ*L_SEQ, nullptr, nullptr, nullptr, inv_sqrt_d};
    launch_gemm(1, p, L_SEQ, L_SEQ, NH);

    // ---- row sums + head<15 numerators ----
    attn_reduce<<<dim3(L_SEQ, NH), 256>>>(E, v0, den, yc);

    // ---- A15 = E15 @ v15 / den15 -> yc[:,15:143] ----
    t_v15<<<(L_SEQ * DA) / 256, 256>>>(v15, v15t);
    p = GP{E + (long)15*L_SEQ*L_SEQ, L_SEQ, 0, v15t, L_SEQ, 0, L_SEQ, nullptr, 0,
           yc, 256, 0, nullptr, nullptr, den + 15*L_SEQ, 0.f};
    launch_gemm(2, p, L_SEQ, DA, 1);

    // ---- x2 = 2x + yc @ Wo' + bo ----
    p = GP{yc, 256, 0, Wot, 256, 0, 256, bo, 0, x2, DE, 0,
           x, nullptr, nullptr, 0.f};
    launch_gemm(3, p, L_SEQ, DE, 1);

    // ---- LN2 ----
    ln_kernel<<<L_SEQ, 256>>>(x2, gamma2, beta2, xn2, xn2f);

    // ---- h1 = gelu(xn2 @ W1 + b1) ----
    p = GP{xn2, DE, 0, W1t, DE, 0, DE, b1, 0, h1, DMLP, 0,
           nullptr, nullptr, nullptr, 0.f};
    launch_gemm(4, p, L_SEQ, DMLP, 1);

    // ---- out = h1 @ W2 + b2 + x2 + xn2 ----
    p = GP{h1, DMLP, 0, W2t, DMLP, 0, DMLP, b2, 0, out, DE, 0,
           x2, xn2f, nullptr, 0.f};
    launch_gemm(5, p, L_SEQ, DE, 1);
}

// round 3
// speedup vs baseline: 1.2018x; 1.2018x over previous
#include <cuda_runtime.h>
#include <cuda_bf16.h>
#include <cstdint>

#define L_SEQ 2048
#define DE    2048
#define DMLP  8192
#define NH    16
#define DA    128

#define BM 128
#define BN 128
#define BK 64
#define STAGE_BYTES (BM*128 + BN*128)          // 64 KB per stage (A+B)
#define GEMM_SMEM   (3*STAGE_BYTES)            // 196608 bytes, 3-stage

// ---------------- static device scratch (allocation-free) ----------------
static __device__ __align__(256) __nv_bfloat16 g_xn1 [(size_t)L_SEQ*DE];
static __device__ __align__(256) __nv_bfloat16 g_xn2 [(size_t)L_SEQ*DE];
static __device__ __align__(256) float         g_xn2f[(size_t)L_SEQ*DE];
static __device__ __align__(256) float         g_x2  [(size_t)L_SEQ*DE];
static __device__ __align__(256) __nv_bfloat16 g_Wqt [(size_t)NH*DA*DE];
static __device__ __align__(256) __nv_bfloat16 g_Wkt [(size_t)NH*DA*DE];
static __device__ __align__(256) __nv_bfloat16 g_Wv15t[(size_t)DA*DE];
static __device__ __align__(256) float         g_Wv0 [(size_t)15*DE];
static __device__ __align__(256) float         g_v0  [(size_t)15*L_SEQ];
static __device__ __align__(256) __nv_bfloat16 g_q   [(size_t)NH*L_SEQ*DA];
static __device__ __align__(256) __nv_bfloat16 g_k   [(size_t)NH*L_SEQ*DA];
static __device__ __align__(256) __nv_bfloat16 g_v15 [(size_t)L_SEQ*DA];
static __device__ __align__(256) __nv_bfloat16 g_v15t[(size_t)DA*L_SEQ];
static __device__ __align__(256) __nv_bfloat16 g_E15 [(size_t)L_SEQ*L_SEQ];
static __device__ __align__(256) float         g_den [(size_t)NH*L_SEQ];
static __device__ __align__(256) float         g_num [(size_t)15*L_SEQ];
static __device__ __align__(256) float         g_a15 [(size_t)L_SEQ*DA];
static __device__ __align__(256) __nv_bfloat16 g_yc  [(size_t)L_SEQ*256];
static __device__ __align__(256) __nv_bfloat16 g_Wot [(size_t)DE*256];
static __device__ __align__(256) __nv_bfloat16 g_W1t [(size_t)DMLP*DE];
static __device__ __align__(256) __nv_bfloat16 g_W2t [(size_t)DE*DMLP];
static __device__ __align__(256) __nv_bfloat16 g_h1  [(size_t)L_SEQ*DMLP];

// ---------------- helpers ----------------
__device__ __forceinline__ void cpasync16(uint32_t dst, const void* src) {
    asm volatile("cp.async.cg.shared.global [%0], [%1], 16;\n" :: "r"(dst), "l"(src));
}
__device__ __forceinline__ void cpcommit() { asm volatile("cp.async.commit_group;\n"); }
template<int N> __device__ __forceinline__ void cpwait() {
    asm volatile("cp.async.wait_group %0;\n" :: "n"(N));
}
__device__ __forceinline__ void ldsm4(uint32_t* r, uint32_t addr) {
    asm volatile("ldmatrix.sync.aligned.m8n8.x4.shared.b16 {%0,%1,%2,%3}, [%4];\n"
                 : "=r"(r[0]), "=r"(r[1]), "=r"(r[2]), "=r"(r[3]) : "r"(addr));
}
__device__ __forceinline__ void mma16816(float* c, const uint32_t* a, uint32_t b0, uint32_t b1) {
    asm volatile("mma.sync.aligned.m16n8k16.row.col.f32.bf16.bf16.f32 "
                 "{%0,%1,%2,%3}, {%4,%5,%6,%7}, {%8,%9}, {%0,%1,%2,%3};\n"
                 : "+f"(c[0]), "+f"(c[1]), "+f"(c[2]), "+f"(c[3])
                 : "r"(a[0]), "r"(a[1]), "r"(a[2]), "r"(a[3]), "r"(b0), "r"(b1));
}
__device__ __forceinline__ float fast_exp(float t) {
    if (fabsf(t) < 0.25f) return 1.f + t * (1.f + t * (0.5f + t * 0.16666667f));
    return expf(t);
}
__device__ __forceinline__ float gelu_tanh(float u) {
    float u2 = u * u;
    float w  = 0.7978845608028654f * u * (1.f + 0.044715f * u2);
    float t;
    if (fabsf(w) < 0.5f) {
        float w2 = w * w;
        t = w * (1.f - w2 * (0.33333333f - w2 * (0.13333333f - w2 * 0.05396825f)));
    } else {
        t = tanhf(w);
    }
    return 0.5f * u * (1.f + t);
}

// ---------------- generic bf16 GEMM: C = A(MxK) * B(NxK)^T, f32 accum ----------------
// Epilogues:
// 0: bf16 C = acc + bias[n]
// 1: bf16 C = exp(acc*scale); atomicAdd rowsum into den[gm]          (E head 15)
// 3: f32  C = 2*aux1 + acc + bias[n]
// 4: bf16 C = gelu(acc + bias[n])
// 5: f32  C = acc + bias[n] + aux1 + aux2
// 6: no store; rowsum/v0-dot atomics into den[z*L+gm], num[z*L+gm]   (E heads 0..14)
// 7: atomicAdd f32 C[gm*ldc+gn] += acc                               (split-K A15)
struct GP {
    const __nv_bfloat16* A; int lda; long sA;
    const __nv_bfloat16* B; int ldb; long sB;
    int K;
    const float* bias; int sBias;
    void* C; int ldc; long sC;
    const float* aux1;
    const float* aux2;
    float* den;
    float* num;
    const float* v0;
    float scale;
};

template<int EPI>
__global__ void __launch_bounds__(256) gemm_bf16(GP p) {
    extern __shared__ __align__(128) char smem[];
    const int tid = threadIdx.x;
    const int bm = blockIdx.x * BM;
    const int bn = blockIdx.y * BN;
    const int z  = blockIdx.z;

    const __nv_bfloat16* Ag = p.A + (long)z * p.sA;
    const __nv_bfloat16* Bg = p.B + (long)z * p.sB;

    uint32_t sbase = (uint32_t)__cvta_generic_to_shared(smem);

    const int lr = tid >> 3;      // 0..31
    const int lc = tid & 7;       // 16B chunk 0..7
    const __nv_bfloat16* Agp = Ag + (long)(bm + lr) * p.lda + lc * 8;
    const __nv_bfloat16* Bgp = Bg + (long)(bn + lr) * p.ldb + lc * 8;

    float c[2][8][4];
    #pragma unroll
    for (int i = 0; i < 2; i++)
        #pragma unroll
        for (int j = 0; j < 8; j++)
            #pragma unroll
            for (int r = 0; r < 4; r++) c[i][j][r] = 0.f;

    const int KT = p.K / BK;

    auto issue = [&](int kt, int s) {
        uint32_t aS = sbase + s * STAGE_BYTES;
        uint32_t bS = aS + BM * 128;
        const __nv_bfloat16* Ak = Agp + kt * BK;
        const __nv_bfloat16* Bk = Bgp + kt * BK;
        #pragma unroll
        for (int i = 0; i < 4; i++) {
            int r = lr + 32 * i;
            cpasync16(aS + r * 128 + ((lc * 16) ^ ((r & 7) * 16)), Ak + (long)(32 * i) * p.lda);
        }
        #pragma unroll
        for (int i = 0; i < 4; i++) {
            int r = lr + 32 * i;
            cpasync16(bS + r * 128 + ((lc * 16) ^ ((r & 7) * 16)), Bk + (long)(32 * i) * p.ldb);
        }
        cpcommit();
    };

    issue(0, 0);
    if (KT > 1) issue(1, 1);

    const int lane = tid & 31, warp = tid >> 5;
    const int wm = warp & 3, wn = warp >> 2;

    for (int kt = 0; kt < KT; kt++) {
        if (kt < KT - 1) cpwait<1>(); else cpwait<0>();
        __syncthreads();
        if (kt + 2 < KT) issue(kt + 2, (kt + 2) % 3);

        uint32_t aS = sbase + (kt % 3) * STAGE_BYTES;
        uint32_t bS = aS + BM * 128;
        #pragma unroll
        for (int ks = 0; ks < 4; ks++) {
            uint32_t a[2][4];
            #pragma unroll
            for (int i = 0; i < 2; i++) {
                int r  = wm * 32 + i * 16 + (lane & 15);
                int cb = ks * 32 + ((lane >> 4) << 4);
                ldsm4(a[i], aS + r * 128 + (cb ^ ((r & 7) << 4)));
            }
            #pragma unroll
            for (int j4 = 0; j4 < 4; j4++) {
                uint32_t b[4];
                int n  = wn * 64 + j4 * 16 + ((lane >> 4) << 3) + (lane & 7);
                int cb = ks * 32 + (((lane >> 3) & 1) << 4);
                ldsm4(b, bS + n * 128 + (cb ^ ((n & 7) << 4)));
                #pragma unroll
                for (int i = 0; i < 2; i++) {
                    mma16816(c[i][2 * j4],     a[i], b[0], b[1]);
                    mma16816(c[i][2 * j4 + 1], a[i], b[2], b[3]);
                }
            }
        }
    }

    const int row0 = lane >> 2, col0 = (lane & 3) * 2;

    if (EPI == 1 || EPI == 6) {
        const float* vv = (EPI == 6) ? (p.v0 + (long)z * L_SEQ) : nullptr;
        __nv_bfloat16* C = (__nv_bfloat16*)p.C;
        #pragma unroll
        for (int i = 0; i < 2; i++)
            #pragma unroll
            for (int h2 = 0; h2 < 2; h2++) {
                long gm = bm + wm * 32 + i * 16 + h2 * 8 + row0;
                float se = 0.f, sn = 0.f;
                #pragma unroll
                for (int j = 0; j < 8; j++) {
                    long gn = bn + wn * 64 + j * 8 + col0;
                    float e0 = fast_exp(c[i][j][h2 * 2 + 0] * p.scale);
                    float e1 = fast_exp(c[i][j][h2 * 2 + 1] * p.scale);
                    se += e0 + e1;
                    if (EPI == 6) sn += e0 * vv[gn] + e1 * vv[gn + 1];
                    if (EPI == 1) {
                        __nv_bfloat162 pk;
                        pk.x = __float2bfloat16(e0); pk.y = __float2bfloat16(e1);
                        *reinterpret_cast<__nv_bfloat162*>(&C[gm * p.ldc + gn]) = pk;
                    }
                }
                se += __shfl_xor_sync(0xffffffffu, se, 1);
                se += __shfl_xor_sync(0xffffffffu, se, 2);
                if (EPI == 6) {
                    sn += __shfl_xor_sync(0xffffffffu, sn, 1);
                    sn += __shfl_xor_sync(0xffffffffu, sn, 2);
                }
                if ((lane & 3) == 0) {
                    if (EPI == 1) atomicAdd(&p.den[gm], se);
                    else {
                        atomicAdd(&p.den[(long)z * L_SEQ + gm], se);
                        atomicAdd(&p.num[(long)z * L_SEQ + gm], sn);
                    }
                }
            }
        return;
    }

    #pragma unroll
    for (int i = 0; i < 2; i++)
        #pragma unroll
        for (int j = 0; j < 8; j++)
            #pragma unroll
            for (int h2 = 0; h2 < 2; h2++) {
                long gm = bm + wm * 32 + i * 16 + h2 * 8 + row0;
                long gn = bn + wn * 64 + j * 8 + col0;
                float a0 = c[i][j][h2 * 2 + 0];
                float a1 = c[i][j][h2 * 2 + 1];

                if (EPI == 0 || EPI == 4) {
                    __nv_bfloat16* C = (__nv_bfloat16*)p.C + (long)z * p.sC;
                    const float* bias = p.bias + (long)z * p.sBias;
                    float x0 = a0 + bias[gn], x1 = a1 + bias[gn + 1];
                    if (EPI == 4) { x0 = gelu_tanh(x0); x1 = gelu_tanh(x1); }
                    __nv_bfloat162 pk;
                    pk.x = __float2bfloat16(x0); pk.y = __float2bfloat16(x1);
                    *reinterpret_cast<__nv_bfloat162*>(&C[gm * p.ldc + gn]) = pk;
                } else if (EPI == 3) {
                    float* C = (float*)p.C;
                    long i0 = gm * p.ldc + gn;
                    C[i0]     = 2.f * p.aux1[i0]     + a0 + p.bias[gn];
                    C[i0 + 1] = 2.f * p.aux1[i0 + 1] + a1 + p.bias[gn + 1];
                } else if (EPI == 5) {
                    float* C = (float*)p.C;
                    long i0 = gm * p.ldc + gn;
                    C[i0]     = a0 + p.bias[gn]     + p.aux1[i0]     + p.aux2[i0];
                    C[i0 + 1] = a1 + p.bias[gn + 1] + p.aux1[i0 + 1] + p.aux2[i0 + 1];
                } else if (EPI == 7) {
                    float* C = (float*)p.C;
                    long i0 = gm * p.ldc + gn;
                    atomicAdd(&C[i0],     a0);
                    atomicAdd(&C[i0 + 1], a1);
                }
            }
}

// ---------------- layernorm (population std, matches jnp.std) ----------------
__global__ void ln_kernel(const float* __restrict__ x, const float* __restrict__ g,
                          const float* __restrict__ b, __nv_bfloat16* ob, float* of) {
    int l = blockIdx.x, tid = threadIdx.x;
    const float* row = x + (long)l * DE;
    float v[8], s = 0.f, s2 = 0.f;
    #pragma unroll
    for (int j = 0; j < 8; j++) {
        v[j] = row[tid + 256 * j];
        s += v[j]; s2 += v[j] * v[j];
    }
    __shared__ float sm[18];
    #pragma unroll
    for (int o = 16; o; o >>= 1) {
        s  += __shfl_xor_sync(0xffffffffu, s,  o);
        s2 += __shfl_xor_sync(0xffffffffu, s2, o);
    }
    if ((tid & 31) == 0) { sm[tid >> 5] = s; sm[(tid >> 5) + 8] = s2; }
    __syncthreads();
    if (tid == 0) {
        float a = 0.f, q = 0.f;
        #pragma unroll
        for (int i = 0; i < 8; i++) { a += sm[i]; q += sm[i + 8]; }
        float mean = a / DE;
        float var  = q / DE - mean * mean;
        float sd   = sqrtf(fmaxf(var, 0.f));
        if (sd == 0.f) sd = 1.f;
        sm[16] = mean; sm[17] = 1.f / sd;
    }
    __syncthreads();
    float mean = sm[16], rs = sm[17];
    #pragma unroll
    for (int j = 0; j < 8; j++) {
        int col = tid + 256 * j;
        float y = g[col] * ((v[j] - mean) * rs) + b[col];
        ob[(long)l * DE + col] = __float2bfloat16(y);
        if (of) of[(long)l * DE + col] = y;
    }
}

// ---------------- v0 matvecs: v0[h][l] = xn1[l]·Wv[h][:,0] + bv[h][0], h<15 ----------------
__global__ void v0_kernel(const __nv_bfloat16* __restrict__ xn1, const float* __restrict__ Wv0,
                          const float* __restrict__ bv, float* __restrict__ v0) {
    int l = blockIdx.x, tid = threadIdx.x;
    __shared__ float xr[DE];
    __shared__ float sm[8];
    for (int k = tid; k < DE; k += 256) xr[k] = __bfloat162float(xn1[(long)l * DE + k]);
    __syncthreads();
    for (int h = 0; h < 15; h++) {
        const float* w = Wv0 + (long)h * DE;
        float p = 0.f;
        for (int k = tid; k < DE; k += 256) p += xr[k] * w[k];
        #pragma unroll
        for (int o = 16; o; o >>= 1) p += __shfl_xor_sync(0xffffffffu, p, o);
        if ((tid & 31) == 0) sm[tid >> 5] = p;
        __syncthreads();
        if (tid == 0) {
            float a = 0.f;
            #pragma unroll
            for (int i = 0; i < 8; i++) a += sm[i];
            v0[(long)h * L_SEQ + l] = a + bv[h * DA];
        }
        __syncthreads();
    }
}

// ---------------- weight prep: vectorized fp32->bf16 transpose ----------------
// src (R, C) f32 row-major -> dst (C, R) bf16 row-major. Tile 64 rows x 32 cols.
__global__ void transpose_cvt(const float* __restrict__ src, __nv_bfloat16* __restrict__ dst,
                              int R, int C, long sS, long sD) {
    __shared__ float t[32][65];
    src += (long)blockIdx.z * sS;
    dst += (long)blockIdx.z * sD;
    int c0 = blockIdx.x * 32, r0 = blockIdx.y * 64;
    int tid = threadIdx.x;
    #pragma unroll
    for (int j = 0; j < 2; j++) {
        int idx = tid + 256 * j;     // 0..511
        int r   = idx >> 3;          // 0..63
        int c4  = idx & 7;           // 0..7
        float4 v = *reinterpret_cast<const float4*>(src + (long)(r0 + r) * C + c0 + c4 * 4);
        t[c4 * 4 + 0][r] = v.x; t[c4 * 4 + 1][r] = v.y;
        t[c4 * 4 + 2][r] = v.z; t[c4 * 4 + 3][r] = v.w;
    }
    __syncthreads();
    #pragma unroll
    for (int j = 0; j < 4; j++) {
        int idx = tid + 256 * j;     // 0..1023
        int c   = idx >> 5;          // 0..31
        int rp  = idx & 31;          // 0..31
        __nv_bfloat162 pk;
        pk.x = __float2bfloat16(t[c][2 * rp]);
        pk.y = __float2bfloat16(t[c][2 * rp + 1]);
        *reinterpret_cast<__nv_bfloat162*>(dst + (long)(c0 + c) * R + r0 + 2 * rp) = pk;
    }
}

__global__ void wo_prep(const float* __restrict__ Wo, __nv_bfloat16* __restrict__ Wot) {
    long idx = (long)blockIdx.x * 256 + threadIdx.x;   // over 256*2048
    int k = (int)(idx >> 11), n = (int)(idx & 2047);
    float v = (k < 143) ? Wo[(long)k * DE + n] : 0.f;
    Wot[(long)n * 256 + k] = __float2bfloat16(v);
}

__global__ void wv0_prep(const float* __restrict__ Wv, float* __restrict__ Wv0) {
    long idx = (long)blockIdx.x * 256 + threadIdx.x;   // over 15*2048
    if (idx < 15 * DE) {
        long h = idx / DE, k = idx % DE;
        Wv0[idx] = Wv[(h * DE + k) * DA];
    }
}

// v15 (2048,128) bf16 -> v15t (128,2048), smem transpose
__global__ void t_v15(const __nv_bfloat16* __restrict__ src, __nv_bfloat16* __restrict__ dst) {
    __shared__ __nv_bfloat16 t[32][34];
    int c0 = blockIdx.x * 32;   // src col
    int r0 = blockIdx.y * 32;   // src row
    int tid = threadIdx.x;      // 256
    #pragma unroll
    for (int j = 0; j < 2; j++) {
        int idx = tid + 256 * j;  // 0..511
        int r  = idx >> 4;        // 0..31
        int c2 = idx & 15;        // 0..15
        __nv_bfloat162 v = *reinterpret_cast<const __nv_bfloat162*>(
            src + (long)(r0 + r) * DA + c0 + 2 * c2);
        t[2 * c2][r] = v.x; t[2 * c2 + 1][r] = v.y;
    }
    __syncthreads();
    #pragma unroll
    for (int j = 0; j < 2; j++) {
        int idx = tid + 256 * j;
        int c  = idx >> 4;
        int rp = idx & 15;
        __nv_bfloat162 pk;
        pk.x = t[c][2 * rp]; pk.y = t[c][2 * rp + 1];
        *reinterpret_cast<__nv_bfloat162*>(dst + (long)(c0 + c) * L_SEQ + r0 + 2 * rp) = pk;
    }
}

// yc[:,0..14] = num/den
__global__ void finalize_cols(const float* __restrict__ num, const float* __restrict__ den,
                              __nv_bfloat16* __restrict__ yc) {
    int idx = blockIdx.x * 256 + threadIdx.x;   // 15*2048
    if (idx < 15 * L_SEQ) {
        int h = idx / L_SEQ, l = idx % L_SEQ;
        yc[(long)l * 256 + h] = __float2bfloat16(num[idx] / den[(long)h * L_SEQ + l]);
    }
}

// yc[:,15..142] = a15/den15
__global__ void finalize15(const float* __restrict__ a15, const float* __restrict__ den15,
                           __nv_bfloat16* __restrict__ yc) {
    int idx = blockIdx.x * 256 + threadIdx.x;   // L*128
    int l = idx >> 7, v = idx & 127;
    yc[(long)l * 256 + 15 + v] = __float2bfloat16(a15[idx] / den15[l]);
}

// ---------------- host launcher ----------------
static void launch_gemm(int epi, const GP& p, int M, int N, int Z) {
    dim3 grid(M / BM, N / BN, Z), block(256);
    switch (epi) {
        case 0: cudaFuncSetAttribute(gemm_bf16<0>, cudaFuncAttributeMaxDynamicSharedMemorySize, GEMM_SMEM);
                gemm_bf16<0><<<grid, block, GEMM_SMEM>>>(p); break;
        case 1: cudaFuncSetAttribute(gemm_bf16<1>, cudaFuncAttributeMaxDynamicSharedMemorySize, GEMM_SMEM);
                gemm_bf16<1><<<grid, block, GEMM_SMEM>>>(p); break;
        case 3: cudaFuncSetAttribute(gemm_bf16<3>, cudaFuncAttributeMaxDynamicSharedMemorySize, GEMM_SMEM);
                gemm_bf16<3><<<grid, block, GEMM_SMEM>>>(p); break;
        case 4: cudaFuncSetAttribute(gemm_bf16<4>, cudaFuncAttributeMaxDynamicSharedMemorySize, GEMM_SMEM);
                gemm_bf16<4><<<grid, block, GEMM_SMEM>>>(p); break;
        case 5: cudaFuncSetAttribute(gemm_bf16<5>, cudaFuncAttributeMaxDynamicSharedMemorySize, GEMM_SMEM);
                gemm_bf16<5><<<grid, block, GEMM_SMEM>>>(p); break;
        case 6: cudaFuncSetAttribute(gemm_bf16<6>, cudaFuncAttributeMaxDynamicSharedMemorySize, GEMM_SMEM);
                gemm_bf16<6><<<grid, block, GEMM_SMEM>>>(p); break;
        case 7: cudaFuncSetAttribute(gemm_bf16<7>, cudaFuncAttributeMaxDynamicSharedMemorySize, GEMM_SMEM);
                gemm_bf16<7><<<grid, block, GEMM_SMEM>>>(p); break;
    }
}

extern "C" void kernel_launch(void* const* d_in, const int* in_sizes, int n_in,
                              void* d_out, int out_size) {
    const float* x      = (const float*)d_in[0];
    const float* Wq     = (const float*)d_in[1];
    const float* bq     = (const float*)d_in[2];
    const float* Wk     = (const float*)d_in[3];
    const float* bk     = (const float*)d_in[4];
    const float* Wv     = (const float*)d_in[5];
    const float* bv     = (const float*)d_in[6];
    const float* Wo     = (const float*)d_in[7];
    const float* bo     = (const float*)d_in[8];
    const float* gamma1 = (const float*)d_in[9];
    const float* beta1  = (const float*)d_in[10];
    const float* gamma2 = (const float*)d_in[11];
    const float* beta2  = (const float*)d_in[12];
    const float* W1     = (const float*)d_in[13];
    const float* b1     = (const float*)d_in[14];
    const float* W2     = (const float*)d_in[15];
    const float* b2     = (const float*)d_in[16];
    float* out = (float*)d_out;

    void *p_xn1, *p_xn2, *p_xn2f, *p_x2, *p_Wqt, *p_Wkt, *p_Wv15t, *p_Wv0, *p_v0;
    void *p_q, *p_k, *p_v15, *p_v15t, *p_E15, *p_den, *p_num, *p_a15;
    void *p_yc, *p_Wot, *p_W1t, *p_W2t, *p_h1;
    cudaGetSymbolAddress(&p_xn1, g_xn1);   cudaGetSymbolAddress(&p_xn2, g_xn2);
    cudaGetSymbolAddress(&p_xn2f, g_xn2f); cudaGetSymbolAddress(&p_x2, g_x2);
    cudaGetSymbolAddress(&p_Wqt, g_Wqt);   cudaGetSymbolAddress(&p_Wkt, g_Wkt);
    cudaGetSymbolAddress(&p_Wv15t, g_Wv15t); cudaGetSymbolAddress(&p_Wv0, g_Wv0);
    cudaGetSymbolAddress(&p_v0, g_v0);     cudaGetSymbolAddress(&p_q, g_q);
    cudaGetSymbolAddress(&p_k, g_k);       cudaGetSymbolAddress(&p_v15, g_v15);
    cudaGetSymbolAddress(&p_v15t, g_v15t); cudaGetSymbolAddress(&p_E15, g_E15);
    cudaGetSymbolAddress(&p_den, g_den);   cudaGetSymbolAddress(&p_num, g_num);
    cudaGetSymbolAddress(&p_a15, g_a15);   cudaGetSymbolAddress(&p_yc, g_yc);
    cudaGetSymbolAddress(&p_Wot, g_Wot);   cudaGetSymbolAddress(&p_W1t, g_W1t);
    cudaGetSymbolAddress(&p_W2t, g_W2t);   cudaGetSymbolAddress(&p_h1, g_h1);

    __nv_bfloat16* xn1  = (__nv_bfloat16*)p_xn1;
    __nv_bfloat16* xn2  = (__nv_bfloat16*)p_xn2;
    float* xn2f = (float*)p_xn2f;
    float* x2   = (float*)p_x2;
    __nv_bfloat16* Wqt  = (__nv_bfloat16*)p_Wqt;
    __nv_bfloat16* Wkt  = (__nv_bfloat16*)p_Wkt;
    __nv_bfloat16* Wv15t= (__nv_bfloat16*)p_Wv15t;
    float* Wv0  = (float*)p_Wv0;
    float* v0   = (float*)p_v0;
    __nv_bfloat16* q    = (__nv_bfloat16*)p_q;
    __nv_bfloat16* k    = (__nv_bfloat16*)p_k;
    __nv_bfloat16* v15  = (__nv_bfloat16*)p_v15;
    __nv_bfloat16* v15t = (__nv_bfloat16*)p_v15t;
    __nv_bfloat16* E15  = (__nv_bfloat16*)p_E15;
    float* den  = (float*)p_den;
    float* num  = (float*)p_num;
    float* a15  = (float*)p_a15;
    __nv_bfloat16* yc   = (__nv_bfloat16*)p_yc;
    __nv_bfloat16* Wot  = (__nv_bfloat16*)p_Wot;
    __nv_bfloat16* W1t  = (__nv_bfloat16*)p_W1t;
    __nv_bfloat16* W2t  = (__nv_bfloat16*)p_W2t;
    __nv_bfloat16* h1   = (__nv_bfloat16*)p_h1;

    // ---- zero accumulators / yc (graph-capturable async memsets) ----
    cudaMemsetAsync(den, 0, (size_t)NH * L_SEQ * sizeof(float));
    cudaMemsetAsync(num, 0, (size_t)15 * L_SEQ * sizeof(float));
    cudaMemsetAsync(a15, 0, (size_t)L_SEQ * DA * sizeof(float));
    cudaMemsetAsync(yc,  0, (size_t)L_SEQ * 256 * sizeof(__nv_bfloat16));

    // ---- weight prep ----
    transpose_cvt<<<dim3(DA/32, DE/64, NH), 256>>>(Wq, Wqt, DE, DA, (long)DE*DA, (long)DA*DE);
    transpose_cvt<<<dim3(DA/32, DE/64, NH), 256>>>(Wk, Wkt, DE, DA, (long)DE*DA, (long)DA*DE);
    transpose_cvt<<<dim3(DA/32, DE/64, 1),  256>>>(Wv + (long)15*DE*DA, Wv15t, DE, DA, 0, 0);
    transpose_cvt<<<dim3(DMLP/32, DE/64, 1), 256>>>(W1, W1t, DE, DMLP, 0, 0);
    transpose_cvt<<<dim3(DE/32, DMLP/64, 1), 256>>>(W2, W2t, DMLP, DE, 0, 0);
    wo_prep<<<(256 * DE) / 256, 256>>>(Wo, Wot);
    wv0_prep<<<(15 * DE + 255) / 256, 256>>>(Wv, Wv0);

    // ---- LN1 ----
    ln_kernel<<<L_SEQ, 256>>>(x, gamma1, beta1, xn1, nullptr);

    GP p{};
    const float inv_sqrt_d = 0.08838834764831845f;

    // ---- Q = xn1 @ Wq + bq (batched heads) ----
    p = GP{xn1, DE, 0, Wqt, DE, (long)DA*DE, DE, bq, DA, q, DA, (long)L_SEQ*DA,
           nullptr, nullptr, nullptr, nullptr, nullptr, 0.f};
    launch_gemm(0, p, L_SEQ, DA, NH);
    // ---- K ----
    p = GP{xn1, DE, 0, Wkt, DE, (long)DA*DE, DE, bk, DA, k, DA, (long)L_SEQ*DA,
           nullptr, nullptr, nullptr, nullptr, nullptr, 0.f};
    launch_gemm(0, p, L_SEQ, DA, NH);
    // ---- V head 15 ----
    p = GP{xn1, DE, 0, Wv15t, DE, 0, DE, bv + 15*DA, 0, v15, DA, 0,
           nullptr, nullptr, nullptr, nullptr, nullptr, 0.f};
    launch_gemm(0, p, L_SEQ, DA, 1);
    // ---- v0 matvecs (heads 0..14) ----
    v0_kernel<<<L_SEQ, 256>>>(xn1, Wv0, bv, v0);

    // ---- heads 0..14: fused exp + rowsum + v0-dot (no E store) ----
    p = GP{q, DA, (long)L_SEQ*DA, k, DA, (long)L_SEQ*DA, DA, nullptr, 0,
           nullptr, 0, 0, nullptr, nullptr, den, num, v0, inv_sqrt_d};
    launch_gemm(6, p, L_SEQ, L_SEQ, 15);

    // ---- head 15: E15 = exp(qk/sqrt(d)) stored bf16 + rowsum atomics ----
    p = GP{q + (long)15*L_SEQ*DA, DA, 0, k + (long)15*L_SEQ*DA, DA, 0, DA, nullptr, 0,
           E15, L_SEQ, 0, nullptr, nullptr, den + 15*L_SEQ, nullptr, nullptr, inv_sqrt_d};
    launch_gemm(1, p, L_SEQ, L_SEQ, 1);

    // ---- yc cols 0..14 ----
    finalize_cols<<<(15 * L_SEQ + 255) / 256, 256>>>(num, den, yc);

    // ---- A15 = E15 @ v15 (split-K over 8 chunks of 256) ----
    t_v15<<<dim3(DA/32, L_SEQ/32), 256>>>(v15, v15t);
    p = GP{E15, L_SEQ, 256, v15t, L_SEQ, 256, 256, nullptr, 0,
           a15, DA, 0, nullptr, nullptr, nullptr, nullptr, nullptr, 0.f};
    launch_gemm(7, p, L_SEQ, DA, 8);
    finalize15<<<(L_SEQ * DA) / 256, 256>>>(a15, den + 15*L_SEQ, yc);

    // ---- x2 = 2x + yc @ Wo' + bo ----
    p = GP{yc, 256, 0, Wot, 256, 0, 256, bo, 0, x2, DE, 0,
           x, nullptr, nullptr, nullptr, nullptr, 0.f};
    launch_gemm(3, p, L_SEQ, DE, 1);

    // ---- LN2 ----
    ln_kernel<<<L_SEQ, 256>>>(x2, gamma2, beta2, xn2, xn2f);

    // ---- h1 = gelu(xn2 @ W1 + b1) ----
    p = GP{xn2, DE, 0, W1t, DE, 0, DE, b1, 0, h1, DMLP, 0,
           nullptr, nullptr, nullptr, nullptr, nullptr, 0.f};
    launch_gemm(4, p, L_SEQ, DMLP, 1);

    // ---- out = h1 @ W2 + b2 + x2 + xn2 ----
    p = GP{h1, DMLP, 0, W2t, DMLP, 0, DMLP, b2, 0, out, DE, 0,
           x2, xn2f, nullptr, nullptr, nullptr, 0.f};
    launch_gemm(5, p, L_SEQ, DE, 1);
}